// round 3
// baseline (speedup 1.0000x reference)
#include <cuda_runtime.h>
#include <math.h>

#define NN 50000
#define FF 128

// ---------------- scratch (device globals; no allocation) ----------------
__device__ __align__(16) float d_xt1[NN * 64];   // [N][4][16], slot15 = 1.0 (denom carrier)
__device__ float d_aq1[NN * 4];
__device__ float d_ak1[NN * 4];
__device__ __align__(16) float d_agg1[NN * 16];
__device__ float d_h1[NN * 16];
__device__ __align__(16) float d_xt2[NN * 48];   // [N][4][12], slot10 = 1.0, slot11 = 0
__device__ float d_aq2[NN * 4];
__device__ float d_ak2[NN * 4];
__device__ __align__(16) float d_agg2[NN * 12];
__device__ float d_h2[NN * 10];
__device__ float d_CW1[128 * 68];                // cols: 0..59 = W1[r][f][o] (c=r*15+o), 60..63 = W1@q1, 64..67 = W1@k1
__device__ float d_CW2[15 * 48];                 // cols: 0..39 = W2, 40..43 = W2@q2, 44..47 = W2@k2
__device__ float d_stats[64];                    // [0..14] sum1, [16..30] sq1, [32..41] sum2, [48..57] sq2
__device__ float d_bn1s[15], d_bn1b[15], d_bn2s[10], d_bn2b[10];
__device__ float d_c1, d_c2;

// ---------------- helpers ----------------
__device__ __forceinline__ void red4(float* p, float a, float b, float c, float d) {
    asm volatile("red.global.add.v4.f32 [%0], {%1,%2,%3,%4};"
                 :: "l"(p), "f"(a), "f"(b), "f"(c), "f"(d) : "memory");
}

// ---------------- init ----------------
__global__ void k_zero() {
    const int tot = NN * 16 + NN * 12 + 64;
    for (int i = blockIdx.x * blockDim.x + threadIdx.x; i < tot; i += gridDim.x * blockDim.x) {
        if (i < NN * 16)            d_agg1[i] = 0.f;
        else if (i < NN * 28)       d_agg2[i - NN * 16] = 0.f;
        else                        d_stats[i - NN * 28] = 0.f;
    }
}

// ---------------- weight prep ----------------
__global__ void k_build1(const float* __restrict__ W1, const float* __restrict__ q1,
                         const float* __restrict__ k1) {
    int i = blockIdx.x * 256 + threadIdx.x;
    if (i >= 128 * 68) return;
    int f = i / 68, c = i % 68;
    float v;
    if (c < 60) {
        int r = c / 15, o = c % 15;
        v = W1[(r * 128 + f) * 15 + o];
    } else if (c < 64) {
        int r = c - 60; float s = 0.f;
        for (int o = 0; o < 15; ++o) s += W1[(r * 128 + f) * 15 + o] * q1[o];
        v = s;
    } else {
        int r = c - 64; float s = 0.f;
        for (int o = 0; o < 15; ++o) s += W1[(r * 128 + f) * 15 + o] * k1[o];
        v = s;
    }
    d_CW1[i] = v;
}

__global__ void k_build2(const float* __restrict__ W2, const float* __restrict__ q2,
                         const float* __restrict__ k2,
                         const float* __restrict__ We1, const float* __restrict__ e1,
                         const float* __restrict__ We2, const float* __restrict__ e2) {
    int i = blockIdx.x * 256 + threadIdx.x;
    if (i == 0) {
        float s = 0.f;
        for (int o = 0; o < 15; ++o) s += We1[o] * e1[o];
        d_c1 = s;
        float t = 0.f;
        for (int o = 0; o < 10; ++o) t += We2[o] * e2[o];
        d_c2 = t;
    }
    if (i >= 15 * 48) return;
    int f = i / 48, c = i % 48;
    float v;
    if (c < 40) {
        int r = c / 10, o = c % 10;
        v = W2[(r * 15 + f) * 10 + o];
    } else if (c < 44) {
        int r = c - 40; float s = 0.f;
        for (int o = 0; o < 10; ++o) s += W2[(r * 15 + f) * 10 + o] * q2[o];
        v = s;
    } else {
        int r = c - 44; float s = 0.f;
        for (int o = 0; o < 10; ++o) s += W2[(r * 15 + f) * 10 + o] * k2[o];
        v = s;
    }
    d_CW2[i] = v;
}

// ---------------- layer-1 GEMM: [N,128] @ [128,68] ----------------
// 256 threads = 64 node-groups x 4 col-groups; thread owns 4 nodes x 17 cols.
__global__ void __launch_bounds__(256) k_gemm1(const float* __restrict__ x, int n_nodes) {
    __shared__ float xs[256 * 33];   // 256 nodes x 32 f (padded 33)
    __shared__ float ws[32 * 68];
    const int tid = threadIdx.x;
    const int nbase = blockIdx.x * 256;
    const int ng = tid >> 2, cg = tid & 3;

    float acc[4][17];
#pragma unroll
    for (int i = 0; i < 4; ++i)
#pragma unroll
        for (int c = 0; c < 17; ++c) acc[i][c] = 0.f;

    for (int ft = 0; ft < 4; ++ft) {
        for (int i = tid; i < 256 * 32; i += 256) {
            int nl = i >> 5, f = i & 31;
            int n = nbase + nl;
            xs[nl * 33 + f] = (n < n_nodes) ? x[n * FF + ft * 32 + f] : 0.f;
        }
        for (int i = tid; i < 32 * 68; i += 256) ws[i] = d_CW1[ft * 32 * 68 + i];
        __syncthreads();
#pragma unroll 4
        for (int f = 0; f < 32; ++f) {
            float x0 = xs[(ng * 4 + 0) * 33 + f];
            float x1 = xs[(ng * 4 + 1) * 33 + f];
            float x2 = xs[(ng * 4 + 2) * 33 + f];
            float x3 = xs[(ng * 4 + 3) * 33 + f];
#pragma unroll
            for (int c = 0; c < 17; ++c) {
                float w = ws[f * 68 + cg * 17 + c];
                acc[0][c] += x0 * w;
                acc[1][c] += x1 * w;
                acc[2][c] += x2 * w;
                acc[3][c] += x3 * w;
            }
        }
        __syncthreads();
    }

#pragma unroll
    for (int i = 0; i < 4; ++i) {
        int n = nbase + ng * 4 + i;
        if (n >= n_nodes) break;
#pragma unroll
        for (int c = 0; c < 17; ++c) {
            int col = cg * 17 + c;
            float v = acc[i][c];
            if (col < 60)      d_xt1[n * 64 + (col / 15) * 16 + (col % 15)] = v;
            else if (col < 64) d_aq1[n * 4 + col - 60] = v;
            else               d_ak1[n * 4 + col - 64] = v;
        }
        if (cg == 0) {
            d_xt1[n * 64 + 15] = 1.f;
            d_xt1[n * 64 + 31] = 1.f;
            d_xt1[n * 64 + 47] = 1.f;
            d_xt1[n * 64 + 63] = 1.f;
        }
    }
}

// ---------------- edge pass 1 ----------------
__global__ void __launch_bounds__(256) k_edge1(const int* __restrict__ ei, const int* __restrict__ et,
                                               const float* __restrict__ ea, int ne) {
    int e = blockIdx.x * 256 + threadIdx.x;
    if (e >= ne) return;
    int s = ei[e], d = ei[ne + e];
    int r = et[e];
    float a = d_aq1[d * 4 + r] + d_ak1[s * 4 + r] + ea[e] * d_c1;
    a = (a > 0.f) ? a : 0.2f * a;
    float ex = __expf(a);
    const float4* xp = reinterpret_cast<const float4*>(d_xt1 + ((size_t)s * 4 + r) * 16);
    float4 v0 = xp[0], v1 = xp[1], v2 = xp[2], v3 = xp[3];
    float* ag = d_agg1 + (size_t)d * 16;
    red4(ag + 0,  ex * v0.x, ex * v0.y, ex * v0.z, ex * v0.w);
    red4(ag + 4,  ex * v1.x, ex * v1.y, ex * v1.z, ex * v1.w);
    red4(ag + 8,  ex * v2.x, ex * v2.y, ex * v2.z, ex * v2.w);
    red4(ag + 12, ex * v3.x, ex * v3.y, ex * v3.z, ex * v3.w);  // .w lane accumulates denom
}

// ---------------- post layer 1: normalize + bias, BN stats ----------------
__global__ void __launch_bounds__(256) k_post1(const float* __restrict__ b1, int n_nodes) {
    int n = blockIdx.x * 256 + threadIdx.x;
    float h[15];
#pragma unroll
    for (int o = 0; o < 15; ++o) h[o] = 0.f;
    if (n < n_nodes) {
        float inv = 1.f / (d_agg1[n * 16 + 15] + 1e-16f);
#pragma unroll
        for (int o = 0; o < 15; ++o) {
            h[o] = d_agg1[n * 16 + o] * inv + b1[o];
            d_h1[n * 16 + o] = h[o];
        }
    }
    __shared__ float ssum[15], ssq[15];
    if (threadIdx.x < 15) { ssum[threadIdx.x] = 0.f; ssq[threadIdx.x] = 0.f; }
    __syncthreads();
#pragma unroll
    for (int o = 0; o < 15; ++o) {
        float s = h[o], s2 = h[o] * h[o];
        for (int off = 16; off; off >>= 1) {
            s  += __shfl_down_sync(0xffffffffu, s, off);
            s2 += __shfl_down_sync(0xffffffffu, s2, off);
        }
        if ((threadIdx.x & 31) == 0) { atomicAdd(&ssum[o], s); atomicAdd(&ssq[o], s2); }
    }
    __syncthreads();
    if (threadIdx.x < 15)                               atomicAdd(&d_stats[threadIdx.x], ssum[threadIdx.x]);
    else if (threadIdx.x >= 16 && threadIdx.x < 31)     atomicAdd(&d_stats[threadIdx.x], ssq[threadIdx.x - 16]);
}

__global__ void k_bnfin1(const float* __restrict__ g, const float* __restrict__ beta, int n_nodes) {
    int o = threadIdx.x;
    if (o < 15) {
        float invn = 1.f / (float)n_nodes;
        float mean = d_stats[o] * invn;
        float var  = d_stats[16 + o] * invn - mean * mean;
        float sc = g[o] * rsqrtf(var + 1e-5f);
        d_bn1s[o] = sc;
        d_bn1b[o] = beta[o] - mean * sc;
    }
}

// ---------------- layer-2: BN+ELU then [N,15] @ [15,48] ----------------
__global__ void __launch_bounds__(256) k_gemm2(int n_nodes) {
    __shared__ float w2s[720];
    for (int i = threadIdx.x; i < 720; i += 256) w2s[i] = d_CW2[i];
    __syncthreads();
    int n = blockIdx.x * 256 + threadIdx.x;
    if (n >= n_nodes) return;
    float x2[15];
#pragma unroll
    for (int o = 0; o < 15; ++o) {
        float v = d_h1[n * 16 + o] * d_bn1s[o] + d_bn1b[o];
        x2[o] = (v > 0.f) ? v : expm1f(v);
    }
    float outv[48];
#pragma unroll
    for (int c = 0; c < 48; ++c) {
        float s = 0.f;
#pragma unroll
        for (int i = 0; i < 15; ++i) s += x2[i] * w2s[i * 48 + c];
        outv[c] = s;
    }
#pragma unroll
    for (int c = 0; c < 40; ++c) d_xt2[n * 48 + (c / 10) * 12 + (c % 10)] = outv[c];
#pragma unroll
    for (int r = 0; r < 4; ++r) {
        d_aq2[n * 4 + r] = outv[40 + r];
        d_ak2[n * 4 + r] = outv[44 + r];
        d_xt2[n * 48 + r * 12 + 10] = 1.f;
        d_xt2[n * 48 + r * 12 + 11] = 0.f;
    }
}

// ---------------- edge pass 2 ----------------
__global__ void __launch_bounds__(256) k_edge2(const int* __restrict__ ei, const int* __restrict__ et,
                                               const float* __restrict__ ea, int ne) {
    int e = blockIdx.x * 256 + threadIdx.x;
    if (e >= ne) return;
    int s = ei[e], d = ei[ne + e];
    int r = et[e];
    float a = d_aq2[d * 4 + r] + d_ak2[s * 4 + r] + ea[e] * d_c2;
    a = (a > 0.f) ? a : 0.2f * a;
    float ex = __expf(a);
    const float4* xp = reinterpret_cast<const float4*>(d_xt2 + ((size_t)s * 4 + r) * 12);
    float4 v0 = xp[0], v1 = xp[1], v2 = xp[2];
    float* ag = d_agg2 + (size_t)d * 12;
    red4(ag + 0, ex * v0.x, ex * v0.y, ex * v0.z, ex * v0.w);
    red4(ag + 4, ex * v1.x, ex * v1.y, ex * v1.z, ex * v1.w);
    red4(ag + 8, ex * v2.x, ex * v2.y, ex * v2.z, ex * v2.w);  // slot10 = denom, slot11 dummy
}

// ---------------- post layer 2 ----------------
__global__ void __launch_bounds__(256) k_post2(const float* __restrict__ b2, int n_nodes) {
    int n = blockIdx.x * 256 + threadIdx.x;
    float h[10];
#pragma unroll
    for (int o = 0; o < 10; ++o) h[o] = 0.f;
    if (n < n_nodes) {
        float inv = 1.f / (d_agg2[n * 12 + 10] + 1e-16f);
#pragma unroll
        for (int o = 0; o < 10; ++o) {
            h[o] = d_agg2[n * 12 + o] * inv + b2[o];
            d_h2[n * 10 + o] = h[o];
        }
    }
    __shared__ float ssum[10], ssq[10];
    if (threadIdx.x < 10) { ssum[threadIdx.x] = 0.f; ssq[threadIdx.x] = 0.f; }
    __syncthreads();
#pragma unroll
    for (int o = 0; o < 10; ++o) {
        float s = h[o], s2 = h[o] * h[o];
        for (int off = 16; off; off >>= 1) {
            s  += __shfl_down_sync(0xffffffffu, s, off);
            s2 += __shfl_down_sync(0xffffffffu, s2, off);
        }
        if ((threadIdx.x & 31) == 0) { atomicAdd(&ssum[o], s); atomicAdd(&ssq[o], s2); }
    }
    __syncthreads();
    if (threadIdx.x < 10)                               atomicAdd(&d_stats[32 + threadIdx.x], ssum[threadIdx.x]);
    else if (threadIdx.x >= 16 && threadIdx.x < 26)     atomicAdd(&d_stats[48 + threadIdx.x - 16], ssq[threadIdx.x - 16]);
}

__global__ void k_bnfin2(const float* __restrict__ g, const float* __restrict__ beta, int n_nodes) {
    int o = threadIdx.x;
    if (o < 10) {
        float invn = 1.f / (float)n_nodes;
        float mean = d_stats[32 + o] * invn;
        float var  = d_stats[48 + o] * invn - mean * mean;
        float sc = g[o] * rsqrtf(var + 1e-5f);
        d_bn2s[o] = sc;
        d_bn2b[o] = beta[o] - mean * sc;
    }
}

// ---------------- head ----------------
__global__ void __launch_bounds__(256) k_head(const float* __restrict__ wh, const float* __restrict__ bh,
                                              float* __restrict__ out, int n_nodes) {
    int n = blockIdx.x * 256 + threadIdx.x;
    if (n >= n_nodes) return;
    float s = bh[0];
#pragma unroll
    for (int o = 0; o < 10; ++o) {
        float v = d_h2[n * 10 + o] * d_bn2s[o] + d_bn2b[o];
        v = (v > 0.f) ? v : expm1f(v);
        s += v * wh[o];
    }
    out[n] = s;
}

// ---------------- launch ----------------
extern "C" void kernel_launch(void* const* d_in, const int* in_sizes, int n_in,
                              void* d_out, int out_size) {
    const float* x   = (const float*)d_in[0];
    const int*   ei  = (const int*)  d_in[1];
    const int*   et  = (const int*)  d_in[2];
    const float* ea  = (const float*)d_in[3];
    const float* W1  = (const float*)d_in[4];
    const float* q1  = (const float*)d_in[5];
    const float* k1  = (const float*)d_in[6];
    const float* e1  = (const float*)d_in[7];
    const float* We1 = (const float*)d_in[8];
    const float* b1  = (const float*)d_in[9];
    const float* W2  = (const float*)d_in[10];
    const float* q2  = (const float*)d_in[11];
    const float* k2  = (const float*)d_in[12];
    const float* e2  = (const float*)d_in[13];
    const float* We2 = (const float*)d_in[14];
    const float* b2  = (const float*)d_in[15];
    const float* g1  = (const float*)d_in[16];
    const float* bt1 = (const float*)d_in[17];
    const float* g2  = (const float*)d_in[18];
    const float* bt2 = (const float*)d_in[19];
    const float* wh  = (const float*)d_in[20];
    const float* bh  = (const float*)d_in[21];
    float* out = (float*)d_out;

    int n  = in_sizes[0] / FF;
    int ne = in_sizes[1] / 2;

    k_zero<<<2048, 256>>>();
    k_build1<<<(128 * 68 + 255) / 256, 256>>>(W1, q1, k1);
    k_build2<<<3, 256>>>(W2, q2, k2, We1, e1, We2, e2);
    k_gemm1<<<(n + 255) / 256, 256>>>(x, n);
    k_edge1<<<(ne + 255) / 256, 256>>>(ei, et, ea, ne);
    k_post1<<<(n + 255) / 256, 256>>>(b1, n);
    k_bnfin1<<<1, 32>>>(g1, bt1, n);
    k_gemm2<<<(n + 255) / 256, 256>>>(n);
    k_edge2<<<(ne + 255) / 256, 256>>>(ei, et, ea, ne);
    k_post2<<<(n + 255) / 256, 256>>>(b2, n);
    k_bnfin2<<<1, 32>>>(g2, bt2, n);
    k_head<<<(n + 255) / 256, 256>>>(wh, bh, out, n);
}